// round 1
// baseline (speedup 1.0000x reference)
#include <cuda_runtime.h>
#include <math.h>

#define BSZ 2
#define SEQ 2048
#define EMB 2048
#define NH 32
#define HD 64
#define MROWS (BSZ*SEQ)

// Scratch (device globals: allocation-free per harness rules)
__device__ float g_Q[(size_t)MROWS * EMB];
__device__ float g_K[(size_t)MROWS * EMB];
__device__ float g_V[(size_t)MROWS * EMB];
__device__ float g_Ao[(size_t)MROWS * EMB];

// ---------------------------------------------------------------------------
// SGEMM: C[M,N] = A[M,K] @ B[K,N] + bias[N]
// 128x128 tile, BK=16, 256 threads, 8x8 per thread.
// ---------------------------------------------------------------------------
__global__ __launch_bounds__(256, 2)
void sgemm_bias(const float* __restrict__ A, const float* __restrict__ B,
                const float* __restrict__ bias, float* __restrict__ C,
                int M, int N, int K)
{
    const int BM = 128, BN = 128, BK = 16;
    __shared__ float As[BK][BM + 4];
    __shared__ float Bs[BK][BN];

    int tid = threadIdx.x;
    int bm = blockIdx.y * BM;
    int bn = blockIdx.x * BN;
    int tx = tid % 16;
    int ty = tid / 16;

    float acc[8][8];
#pragma unroll
    for (int i = 0; i < 8; i++)
#pragma unroll
        for (int j = 0; j < 8; j++) acc[i][j] = 0.f;

    int arow  = tid / 4;          // 0..63
    int acol4 = (tid % 4) * 4;    // 0,4,8,12
    int brow  = tid / 32;         // 0..7
    int bcol4 = (tid % 32) * 4;   // 0..124

    for (int k0 = 0; k0 < K; k0 += BK) {
#pragma unroll
        for (int r = 0; r < 2; r++) {
            int m = arow + r * 64;
            float4 v = *(const float4*)&A[(size_t)(bm + m) * K + k0 + acol4];
            As[acol4 + 0][m] = v.x;
            As[acol4 + 1][m] = v.y;
            As[acol4 + 2][m] = v.z;
            As[acol4 + 3][m] = v.w;
        }
#pragma unroll
        for (int r = 0; r < 2; r++) {
            int kk = brow + r * 8;
            *(float4*)&Bs[kk][bcol4] =
                *(const float4*)&B[(size_t)(k0 + kk) * N + bn + bcol4];
        }
        __syncthreads();

#pragma unroll
        for (int kk = 0; kk < BK; kk++) {
            float a[8], b[8];
            *(float4*)&a[0] = *(float4*)&As[kk][ty * 8];
            *(float4*)&a[4] = *(float4*)&As[kk][ty * 8 + 4];
            *(float4*)&b[0] = *(float4*)&Bs[kk][tx * 8];
            *(float4*)&b[4] = *(float4*)&Bs[kk][tx * 8 + 4];
#pragma unroll
            for (int i = 0; i < 8; i++)
#pragma unroll
                for (int j = 0; j < 8; j++)
                    acc[i][j] += a[i] * b[j];
        }
        __syncthreads();
    }

#pragma unroll
    for (int i = 0; i < 8; i++) {
        int m = bm + ty * 8 + i;
#pragma unroll
        for (int j = 0; j < 8; j += 4) {
            int n = bn + tx * 8 + j;
            float4 o;
            o.x = acc[i][j + 0] + bias[n + 0];
            o.y = acc[i][j + 1] + bias[n + 1];
            o.z = acc[i][j + 2] + bias[n + 2];
            o.w = acc[i][j + 3] + bias[n + 3];
            *(float4*)&C[(size_t)m * N + n] = o;
        }
    }
}

// ---------------------------------------------------------------------------
// Flash attention, causal. RoPE is skipped: the reference rotates q and k by
// the SAME per-head orthogonal rotation (angle depends only on head index),
// so q.k is exactly invariant, and v is never rotated.
// CTA = (q-block of 64 rows, head, batch). 256 threads, 4x4 micro-tiles.
// ---------------------------------------------------------------------------
#define BQ 64
#define BKV 64
#define SLD 68   // smem row pitch (floats), keeps 16B alignment, de-conflicts

__global__ __launch_bounds__(256, 1)
void flash_attn(const float* __restrict__ Q, const float* __restrict__ K,
                const float* __restrict__ V, float* __restrict__ O)
{
    extern __shared__ float sm[];
    float* Qs = sm;                // [64][SLD]
    float* Ks = Qs + BQ * SLD;
    float* Vs = Ks + BKV * SLD;
    float* Ps = Vs + BKV * SLD;

    int qb = blockIdx.x;
    int h  = blockIdx.y;
    int b  = blockIdx.z;
    int tid = threadIdx.x;
    int tx = tid % 16;
    int ty = tid / 16;
    int q0 = qb * BQ;

    // Load Q tile (64x64)
#pragma unroll
    for (int rr = 0; rr < 4; rr++) {
        int r = ty + rr * 16;
        int c = tx * 4;
        *(float4*)&Qs[r * SLD + c] =
            *(const float4*)&Q[((size_t)(b * SEQ + q0 + r)) * EMB + h * HD + c];
    }

    float m_i[4], l_i[4], o[4][4];
#pragma unroll
    for (int i = 0; i < 4; i++) {
        m_i[i] = -INFINITY;
        l_i[i] = 0.f;
#pragma unroll
        for (int j = 0; j < 4; j++) o[i][j] = 0.f;
    }
    const float scale = 0.125f;  // 1/sqrt(64)

    int nkb = qb + 1;  // causal: only kv blocks up to the diagonal
    for (int kb = 0; kb < nkb; kb++) {
        __syncthreads();  // previous PV done; also covers initial Q load
#pragma unroll
        for (int rr = 0; rr < 4; rr++) {
            int r = ty + rr * 16;
            int c = tx * 4;
            size_t g = ((size_t)(b * SEQ + kb * BKV + r)) * EMB + h * HD + c;
            *(float4*)&Ks[r * SLD + c] = *(const float4*)&K[g];
            *(float4*)&Vs[r * SLD + c] = *(const float4*)&V[g];
        }
        __syncthreads();

        // S = Q K^T (4x4 per thread), vectorized over d
        float s[4][4];
#pragma unroll
        for (int i = 0; i < 4; i++)
#pragma unroll
            for (int j = 0; j < 4; j++) s[i][j] = 0.f;

        for (int d4 = 0; d4 < 16; d4++) {
            float4 qv[4], kv[4];
#pragma unroll
            for (int i = 0; i < 4; i++)
                qv[i] = *(float4*)&Qs[(ty * 4 + i) * SLD + d4 * 4];
#pragma unroll
            for (int j = 0; j < 4; j++)
                kv[j] = *(float4*)&Ks[(tx * 4 + j) * SLD + d4 * 4];
#pragma unroll
            for (int i = 0; i < 4; i++)
#pragma unroll
                for (int j = 0; j < 4; j++)
                    s[i][j] += qv[i].x * kv[j].x + qv[i].y * kv[j].y +
                               qv[i].z * kv[j].z + qv[i].w * kv[j].w;
        }

        // scale + causal mask (only the diagonal tile needs masking)
        bool diag = (kb == qb);
#pragma unroll
        for (int i = 0; i < 4; i++) {
            int qr = q0 + ty * 4 + i;
#pragma unroll
            for (int j = 0; j < 4; j++) {
                s[i][j] *= scale;
                if (diag) {
                    int kc = kb * BKV + tx * 4 + j;
                    if (kc > qr) s[i][j] = -INFINITY;
                }
            }
        }

        // online softmax per row (rows replicated across the 16 tx threads)
#pragma unroll
        for (int i = 0; i < 4; i++) {
            float mx = fmaxf(fmaxf(s[i][0], s[i][1]), fmaxf(s[i][2], s[i][3]));
#pragma unroll
            for (int off = 1; off < 16; off <<= 1)
                mx = fmaxf(mx, __shfl_xor_sync(0xffffffffu, mx, off));
            float m_new = fmaxf(m_i[i], mx);
            float corr = __expf(m_i[i] - m_new);  // 0 on first tile
            m_i[i] = m_new;
            float rs = 0.f;
#pragma unroll
            for (int j = 0; j < 4; j++) {
                float p = __expf(s[i][j] - m_new);
                s[i][j] = p;
                rs += p;
            }
#pragma unroll
            for (int off = 1; off < 16; off <<= 1)
                rs += __shfl_xor_sync(0xffffffffu, rs, off);
            l_i[i] = l_i[i] * corr + rs;
#pragma unroll
            for (int j = 0; j < 4; j++) o[i][j] *= corr;
        }

        // write P to smem
#pragma unroll
        for (int i = 0; i < 4; i++) {
            float4 pv = make_float4(s[i][0], s[i][1], s[i][2], s[i][3]);
            *(float4*)&Ps[(ty * 4 + i) * SLD + tx * 4] = pv;
        }
        __syncthreads();

        // O += P @ V : rows ty*4+i, cols tx*4+j
        for (int kk = 0; kk < BKV; kk++) {
            float4 vv = *(float4*)&Vs[kk * SLD + tx * 4];
#pragma unroll
            for (int i = 0; i < 4; i++) {
                float p = Ps[(ty * 4 + i) * SLD + kk];
                o[i][0] += p * vv.x;
                o[i][1] += p * vv.y;
                o[i][2] += p * vv.z;
                o[i][3] += p * vv.w;
            }
        }
    }

    // normalize + store (head-interleaved layout -> feeds output GEMM directly)
#pragma unroll
    for (int i = 0; i < 4; i++) {
        float inv = 1.f / l_i[i];
        int qr = q0 + ty * 4 + i;
        float4 ov = make_float4(o[i][0] * inv, o[i][1] * inv,
                                o[i][2] * inv, o[i][3] * inv);
        *(float4*)&O[((size_t)(b * SEQ + qr)) * EMB + h * HD + tx * 4] = ov;
    }
}

// ---------------------------------------------------------------------------
// Launch
// ---------------------------------------------------------------------------
extern "C" void kernel_launch(void* const* d_in, const int* in_sizes, int n_in,
                              void* d_out, int out_size)
{
    const float* x  = (const float*)d_in[0];
    const float* Wq = (const float*)d_in[1];
    const float* bq = (const float*)d_in[2];
    const float* Wk = (const float*)d_in[3];
    const float* bk = (const float*)d_in[4];
    const float* Wv = (const float*)d_in[5];
    const float* bv = (const float*)d_in[6];
    const float* Wo = (const float*)d_in[7];
    const float* bo = (const float*)d_in[8];
    float* out = (float*)d_out;

    float *Qp, *Kp, *Vp, *Ap;
    cudaGetSymbolAddress((void**)&Qp, g_Q);
    cudaGetSymbolAddress((void**)&Kp, g_K);
    cudaGetSymbolAddress((void**)&Vp, g_V);
    cudaGetSymbolAddress((void**)&Ap, g_Ao);

    int smem_attn = 4 * BQ * SLD * (int)sizeof(float);  // ~69.6 KB
    cudaFuncSetAttribute(flash_attn, cudaFuncAttributeMaxDynamicSharedMemorySize,
                         smem_attn);

    dim3 gthr(256);
    dim3 ggrid(EMB / 128, MROWS / 128);  // (16, 32)

    // QKV projections (biases included; fp32 exact)
    sgemm_bias<<<ggrid, gthr>>>(x, Wq, bq, Qp, MROWS, EMB, EMB);
    sgemm_bias<<<ggrid, gthr>>>(x, Wk, bk, Kp, MROWS, EMB, EMB);
    sgemm_bias<<<ggrid, gthr>>>(x, Wv, bv, Vp, MROWS, EMB, EMB);

    // Causal attention (RoPE mathematically eliminated — see comment above)
    dim3 agrid(SEQ / BQ, NH, BSZ);  // (32, 32, 2)
    flash_attn<<<agrid, gthr, smem_attn>>>(Qp, Kp, Vp, Ap);

    // Output projection
    sgemm_bias<<<ggrid, gthr>>>(Ap, Wo, bo, out, MROWS, EMB, EMB);
}